// round 15
// baseline (speedup 1.0000x reference)
#include <cuda_runtime.h>
#include <cooperative_groups.h>

namespace cg = cooperative_groups;

namespace {
constexpr int   kB       = 8;
constexpr int   kNT      = 256;
constexpr int   kNZ      = 256;
constexpr int   kNX      = 256;
constexpr int   kNREC    = 64;
constexpr int   kThreads = 512;               // column = tid&255, group = tid>>8
constexpr float kDT2     = 1.0e-6f;           // DT*DT
constexpr float kInvDH2  = 0.01f;             // 1/(DH*DH)

constexpr int smem_floats(int cluster) {
    int rows = kNZ / cluster;
    return 4 * rows * kNX + 512 + kNT + 64 + 64 + 4;
}
constexpr int smem_bytes(int cluster) { return smem_floats(cluster) * 4; }
}

template <int CLUSTER>
__global__ void __launch_bounds__(kThreads, 1)
wave_fd_kernel(const float* __restrict__ x,
               const float* __restrict__ vp,
               const int*   __restrict__ src_loc,
               const int*   __restrict__ rec_loc,
               float*       __restrict__ out)
{
    constexpr int kRows = kNZ / CLUSTER;      // rows per CTA
    constexpr int H     = kRows / 2;          // rows per thread
    constexpr int BUF   = kRows * kNX;        // floats per field buffer
    constexpr int SA    = 4 * BUF;            // staged prev-CTA row (kRows-1) of h^t
    constexpr int SB    = SA + 256;           // staged next-CTA row 0 of h^t
    constexpr int WAV   = SB + 256;
    constexpr int ROFF  = WAV + kNT;
    constexpr int RK    = ROFF + 64;
    constexpr int RCNT  = RK + 64;

    extern __shared__ float sm[];
    int* smi = (int*)sm;

    cg::cluster_group cluster = cg::this_cluster();
    const int rank  = (int)cluster.block_rank();
    const int batch = blockIdx.x / CLUSTER;
    const int tid   = threadIdx.x;
    const int c     = tid & (kNX - 1);        // column
    const int g     = tid >> 8;               // 0 = top half, 1 = bottom half
    const int r0    = rank * kRows;           // CTA's first global row
    const int gr0   = g * H;                  // my first local row
    const int gz0   = r0 + gr0;               // global

    // ---- init: zero all 4 field buffers + stage rows; wavelet; receiver list ----
    for (int i = tid; i < 4 * BUF + 512; i += kThreads) sm[i] = 0.0f;
    if (tid < kNT) sm[WAV + tid] = x[batch * kNT + tid];
    if (tid == 0) smi[RCNT] = 0;
    __syncthreads();
    if (tid < kNREC) {
        int rz = rec_loc[(batch * kNREC + tid) * 2 + 0];
        int rx = rec_loc[(batch * kNREC + tid) * 2 + 1];
        if (rz >= r0 && rz < r0 + kRows) {
            int slot = atomicAdd(&smi[RCNT], 1);
            smi[ROFF + slot] = (rz - r0) * kNX + rx;
            smi[RK   + slot] = tid;
        }
    }
    __syncthreads();

    // hoisted receiver-gather state (static for the whole run)
    const bool isRec = (tid < smi[RCNT]);
    const int  myOff = isRec ? smi[ROFF + tid] : 0;
    const int  myK   = isRec ? smi[RK   + tid] : 0;

    // ---- source ownership (src is always interior: rows/cols 4..251) ----
    const int  sz = src_loc[batch * 2 + 0];
    const int  sx = src_loc[batch * 2 + 1];
    const bool isCol  = (c == sx);
    const int  srcRow = (isCol && sz >= gz0 && sz < gz0 + H) ? (sz - gz0) : -100;
    const bool srcExt = isCol && (g == 0 ? (sz == r0 - 1) : (sz == r0 + kRows));

    // ---- per-cell coefficients with 1/dh^2 folded in (c2 = v^2*dt^2/dh^2) ----
    const float kCF = kDT2 * kInvDH2;
    float c2[H], c2e;
    const bool active = (c > 0) && (c < kNX - 1);
#pragma unroll
    for (int i = 0; i < H; i++) {
        int gz = gz0 + i;
        float v = vp[gz * kNX + c];
        bool dead = !active || gz == 0 || gz == kNZ - 1;
        c2[i] = dead ? 0.0f : v * v * kCF;
    }
    {   // ghost-row coefficient (row r0-1 for g0, row r0+kRows for g1)
        int ge   = (g == 0) ? r0 - 1 : r0 + kRows;
        bool dE  = !active || ge <= 0 || ge >= kNZ - 1;
        int gec  = ge < 0 ? 0 : (ge > kNZ - 1 ? kNZ - 1 : ge);
        float ve = vp[gec * kNX + c];
        c2e = dE ? 0.0f : ve * ve * kCF;
    }

    // ---- register-resident own rows: hE = even-time field, hO = odd-time field ----
    float hE[H], hO[H], extI = 0.0f;
#pragma unroll
    for (int i = 0; i < H; i++) { hE[i] = 0.0f; hO[i] = 0.0f; }

    const int prevRank = (rank == 0) ? 0 : rank - 1;
    const int nextRank = (rank == CLUSTER - 1) ? rank : rank + 1;
    const float* prevS = (const float*)cluster.map_shared_rank((void*)sm, prevRank);
    const float* nextS = (const float*)cluster.map_shared_rank((void*)sm, nextRank);

    cluster.sync();   // all buffers zeroed cluster-wide

    float* const outR = out + batch * kNT * kNREC + myK;   // receiver base (hoisted)

    // One stencil phase over my H rows — byte-identical schedule to the
    // 242us champion (interleaved LDS/FMA/STS, ascending rows, folded coeffs).
    auto phase = [&](const float* sbuf, float* dbuf,
                     float (&hc)[H], float (&hp)[H],
                     float ghTop, float ghBot, float inj) {
        float upB = (g == 0) ? ghTop : sbuf[(gr0 - 1) * kNX + c];
        float dnB = (g == 1) ? ghBot : sbuf[(gr0 + H) * kNX + c];
#pragma unroll
        for (int i = 0; i < H; i++) {
            float up  = (i == 0)     ? upB : hc[i - 1];
            float dn  = (i == H - 1) ? dnB : hc[i + 1];
            float l   = sbuf[(gr0 + i) * kNX + c - 1];
            float r   = sbuf[(gr0 + i) * kNX + c + 1];
            float s2  = (up + dn) + (l + r);
            float lapU = fmaf(hc[i], -4.0f, s2);         // unscaled laplacian
            float base = fmaf(2.0f, hc[i], -hp[i]);      // 2h - h_prev
            float hn   = fmaf(c2[i], lapU, base);        // c2 carries dt^2/dh^2
            if (i == srcRow) hn += inj;
            hp[i] = hn;
            dbuf[(gr0 + i) * kNX + c] = hn;
        }
    };

    // One superstep: t -> t+2 with ONE cluster.sync. Identical structure to
    // the champion; buffer/neighbor pointers are now passed as loop-invariant
    // registers (rotation resolved at compile time by the 2x unroll below).
    auto superstep = [&](int t, const float* cur, float* bufI, float* bufO,
                         const float* pC, const float* pP,
                         const float* nC, const float* nP) {
        // ---- stage radius-2 remote halo (3 values/thread; 1 row via smem for l/r) ----
        float a0, a1, ap;
        if (g == 0) {
            a0 = pC[(kRows - 1) * kNX + c];   // h^t   row r0-1 (ghost center)
            a1 = pC[(kRows - 2) * kNX + c];   // h^t   row r0-2 (ghost's up)
            ap = pP[(kRows - 1) * kNX + c];   // h^t-1 row r0-1
            sm[SA + c] = a0;
        } else {
            a0 = nC[c];                       // h^t   row r0+kRows
            a1 = nC[kNX + c];                 // h^t   row r0+kRows+1
            ap = nP[c];                       // h^t-1 row r0+kRows
            sm[SB + c] = a0;
        }
        __syncthreads();                      // staged rows visible

        const float inj1 = kDT2 * sm[WAV + t];
        const float inj2 = kDT2 * sm[WAV + t + 1];

        // ---- ghost-row intermediate h^{t+1} (register-only, folded coeff) ----
        if (active) {
            const int stg = (g == 0) ? SA : SB;
            float adj  = (g == 0) ? hE[0] : hE[H - 1];   // adjacent own row of h^t
            float s0   = (a1 + adj) + (sm[stg + c - 1] + sm[stg + c + 1]);
            float lapU = fmaf(a0, -4.0f, s0);
            extI = fmaf(c2e, lapU, fmaf(2.0f, a0, -ap));
            if (srcExt) extI += inj1;
        }

        // ---- phase 1: h^{t+1} on my rows ----
        if (active) phase(cur, bufI, hE, hO, a0, a0, inj1);
        __syncthreads();                      // bufI complete CTA-wide

        // receiver gather for step t (reads bufI, own CTA)
        if (isRec) outR[t * kNREC] = bufI[myOff];

        // ---- phase 2: h^{t+2} on my rows (ghosts come from extI registers) ----
        if (active) phase(bufI, bufO, hO, hE, extI, extI, inj2);

        cluster.sync();   // publish bufI (h^{t+1}) + bufO (h^{t+2})

        // receiver gather for step t+1 (bufO not rewritten until 2 supersteps
        // later, ordered after the next cluster.sync > this read)
        if (isRec) outR[(t + 1) * kNREC] = bufO[myOff];
    };

    // loop-invariant rotating buffers (rotation period = 4 time steps = 2 supersteps)
    float* const B0 = sm;            float* const B1 = sm + BUF;
    float* const B2 = sm + 2 * BUF;  float* const B3 = sm + 3 * BUF;
    const float* const P0 = prevS;           const float* const P1 = prevS + BUF;
    const float* const P2 = prevS + 2 * BUF; const float* const P3 = prevS + 3 * BUF;
    const float* const N0 = nextS;           const float* const N1 = nextS + BUF;
    const float* const N2 = nextS + 2 * BUF; const float* const N3 = nextS + 3 * BUF;

    // Rotation audit (matches champion's (t&3) indexing):
    //   t%4==0: cur=B0 bufI=B1 bufO=B2, pC=P0 pP=P3
    //   t%4==2: cur=B2 bufI=B3 bufO=B0, pC=P2 pP=P1
    for (int t = 0; t < kNT; t += 4) {
        superstep(t,     B0, B1, B2, P0, P3, N0, N3);
        superstep(t + 2, B2, B3, B0, P2, P1, N2, N1);
    }
}

extern "C" void kernel_launch(void* const* d_in, const int* in_sizes, int n_in,
                              void* d_out, int out_size)
{
    (void)in_sizes; (void)n_in; (void)out_size;
    const float* x   = (const float*)d_in[0];
    const float* vp  = (const float*)d_in[1];
    const int*   src = (const int*)d_in[2];
    const int*   rec = (const int*)d_in[3];
    float*       out = (float*)d_out;

    cudaFuncSetAttribute(wave_fd_kernel<16>,
                         cudaFuncAttributeMaxDynamicSharedMemorySize, smem_bytes(16));
    cudaFuncSetAttribute(wave_fd_kernel<16>,
                         cudaFuncAttributeNonPortableClusterSizeAllowed, 1);
    cudaFuncSetAttribute(wave_fd_kernel<8>,
                         cudaFuncAttributeMaxDynamicSharedMemorySize, smem_bytes(8));

    int maxCluster = 0;
    {
        cudaLaunchConfig_t probe = {};
        probe.gridDim          = dim3(kB * 16, 1, 1);
        probe.blockDim         = dim3(kThreads, 1, 1);
        probe.dynamicSmemBytes = smem_bytes(16);
        cudaOccupancyMaxPotentialClusterSize(&maxCluster, (const void*)wave_fd_kernel<16>, &probe);
    }

    cudaLaunchAttribute attr[1];
    attr[0].id = cudaLaunchAttributeClusterDimension;
    attr[0].val.clusterDim.y = 1;
    attr[0].val.clusterDim.z = 1;

    cudaLaunchConfig_t cfg = {};
    cfg.blockDim = dim3(kThreads, 1, 1);
    cfg.stream   = 0;
    cfg.attrs    = attr;
    cfg.numAttrs = 1;

    if (maxCluster >= 16) {
        cfg.gridDim              = dim3(kB * 16, 1, 1);
        cfg.dynamicSmemBytes     = smem_bytes(16);
        attr[0].val.clusterDim.x = 16;
        cudaLaunchKernelEx(&cfg, wave_fd_kernel<16>, x, vp, src, rec, out);
    } else {
        cfg.gridDim              = dim3(kB * 8, 1, 1);
        cfg.dynamicSmemBytes     = smem_bytes(8);
        attr[0].val.clusterDim.x = 8;
        cudaLaunchKernelEx(&cfg, wave_fd_kernel<8>, x, vp, src, rec, out);
    }
}

// round 16
// speedup vs baseline: 1.4168x; 1.4168x over previous
#include <cuda_runtime.h>
#include <cooperative_groups.h>

namespace cg = cooperative_groups;

namespace {
constexpr int   kB       = 8;
constexpr int   kNT      = 256;
constexpr int   kNZ      = 256;
constexpr int   kNX      = 256;
constexpr int   kNREC    = 64;
constexpr int   kThreads = 512;               // column = tid&255, group = tid>>8
constexpr float kDT2     = 1.0e-6f;           // DT*DT
constexpr float kInvDH2  = 0.01f;             // 1/(DH*DH)

constexpr int smem_floats(int cluster) {
    int rows = kNZ / cluster;
    return 4 * rows * kNX + 512 + kNT + 64 + 64 + 4;
}
constexpr int smem_bytes(int cluster) { return smem_floats(cluster) * 4; }
}

template <int CLUSTER>
__global__ void __launch_bounds__(kThreads, 1)
wave_fd_kernel(const float* __restrict__ x,
               const float* __restrict__ vp,
               const int*   __restrict__ src_loc,
               const int*   __restrict__ rec_loc,
               float*       __restrict__ out)
{
    constexpr int kRows = kNZ / CLUSTER;      // rows per CTA
    constexpr int H     = kRows / 2;          // rows per thread
    constexpr int BUF   = kRows * kNX;        // floats per field buffer
    constexpr int SA    = 4 * BUF;            // staged prev-CTA row (kRows-1) of h^t
    constexpr int SB    = SA + 256;           // staged next-CTA row 0 of h^t
    constexpr int WAV   = SB + 256;
    constexpr int ROFF  = WAV + kNT;
    constexpr int RK    = ROFF + 64;
    constexpr int RCNT  = RK + 64;

    extern __shared__ float sm[];
    int* smi = (int*)sm;

    cg::cluster_group cluster = cg::this_cluster();
    const int rank  = (int)cluster.block_rank();
    const int batch = blockIdx.x / CLUSTER;
    const int tid   = threadIdx.x;
    const int c     = tid & (kNX - 1);        // column
    const int g     = tid >> 8;               // 0 = top half, 1 = bottom half
    const int r0    = rank * kRows;           // CTA's first global row
    const int gr0   = g * H;                  // my first local row
    const int gz0   = r0 + gr0;               // global

    // ---- init: zero all 4 field buffers + stage rows; wavelet; receiver list ----
    for (int i = tid; i < 4 * BUF + 512; i += kThreads) sm[i] = 0.0f;
    if (tid < kNT) sm[WAV + tid] = x[batch * kNT + tid];
    if (tid == 0) smi[RCNT] = 0;
    __syncthreads();
    if (tid < kNREC) {
        int rz = rec_loc[(batch * kNREC + tid) * 2 + 0];
        int rx = rec_loc[(batch * kNREC + tid) * 2 + 1];
        if (rz >= r0 && rz < r0 + kRows) {
            int slot = atomicAdd(&smi[RCNT], 1);
            smi[ROFF + slot] = (rz - r0) * kNX + rx;
            smi[RK   + slot] = tid;
        }
    }
    __syncthreads();
    const int cnt = smi[RCNT];

    // ---- source ownership (src is always interior: rows/cols 4..251) ----
    const int  sz = src_loc[batch * 2 + 0];
    const int  sx = src_loc[batch * 2 + 1];
    const bool isCol  = (c == sx);
    const int  srcRow = (isCol && sz >= gz0 && sz < gz0 + H) ? (sz - gz0) : -100;
    const bool srcExt = isCol && (g == 0 ? (sz == r0 - 1) : (sz == r0 + kRows));

    // ---- per-cell coefficients with 1/dh^2 folded in (c2 = v^2*dt^2/dh^2) ----
    const float kCF = kDT2 * kInvDH2;
    float c2[H], c2e;
    const bool active = (c > 0) && (c < kNX - 1);
#pragma unroll
    for (int i = 0; i < H; i++) {
        int gz = gz0 + i;
        float v = vp[gz * kNX + c];
        bool dead = !active || gz == 0 || gz == kNZ - 1;
        c2[i] = dead ? 0.0f : v * v * kCF;
    }
    {   // ghost-row coefficient (row r0-1 for g0, row r0+kRows for g1)
        int ge   = (g == 0) ? r0 - 1 : r0 + kRows;
        bool dE  = !active || ge <= 0 || ge >= kNZ - 1;
        int gec  = ge < 0 ? 0 : (ge > kNZ - 1 ? kNZ - 1 : ge);
        float ve = vp[gec * kNX + c];
        c2e = dE ? 0.0f : ve * ve * kCF;
    }

    // ---- register-resident own rows: hE = even-time field, hO = odd-time field ----
    float hE[H], hO[H], extI = 0.0f;
#pragma unroll
    for (int i = 0; i < H; i++) { hE[i] = 0.0f; hO[i] = 0.0f; }

    const int prevRank = (rank == 0) ? 0 : rank - 1;
    const int nextRank = (rank == CLUSTER - 1) ? rank : rank + 1;
    const float* prevS = (const float*)cluster.map_shared_rank((void*)sm, prevRank);
    const float* nextS = (const float*)cluster.map_shared_rank((void*)sm, nextRank);

    cluster.sync();   // all buffers zeroed cluster-wide

    float* outB = out + batch * kNT * kNREC;

    // One stencil phase over my H rows — byte-identical body to the 242us
    // champion (interleaved LDS/FMA/STS, ascending rows, folded coeffs).
    auto phase = [&](const float* sbuf, float* dbuf,
                     float (&hc)[H], float (&hp)[H],
                     float ghTop, float ghBot, float inj) {
        float upB = (g == 0) ? ghTop : sbuf[(gr0 - 1) * kNX + c];
        float dnB = (g == 1) ? ghBot : sbuf[(gr0 + H) * kNX + c];
#pragma unroll
        for (int i = 0; i < H; i++) {
            float up  = (i == 0)     ? upB : hc[i - 1];
            float dn  = (i == H - 1) ? dnB : hc[i + 1];
            float l   = sbuf[(gr0 + i) * kNX + c - 1];
            float r   = sbuf[(gr0 + i) * kNX + c + 1];
            float s2  = (up + dn) + (l + r);
            float lapU = fmaf(hc[i], -4.0f, s2);         // unscaled laplacian
            float base = fmaf(2.0f, hc[i], -hp[i]);      // 2h - h_prev
            float hn   = fmaf(c2[i], lapU, base);        // c2 carries dt^2/dh^2
            if (i == srcRow) hn += inj;
            hp[i] = hn;
            dbuf[(gr0 + i) * kNX + c] = hn;
        }
    };

    // Superstep s advances t=2s -> t+2 with ONE cluster.sync and now ONE
    // __syncthreads (merged): staging -> phase1 -> sync -> ghost -> gather ->
    // phase2 -> cluster.sync. The merged barrier orders BOTH the staged
    // SA/SB rows (read by ghost-comp) and bufI (read by gather/phase2);
    // phase 1 never touches SA/SB, so running it before the barrier is safe.
    // a1/ap are consumed only after phase 1 -> their DSMEM latency is hidden.
    for (int s = 0; s < kNT / 2; s++) {
        const int t = 2 * s;
        const float* cur  = sm + (t & 3) * BUF;
        float*       bufI = sm + ((t + 1) & 3) * BUF;
        float*       bufO = sm + ((t + 2) & 3) * BUF;

        // ---- stage radius-2 remote halo (3 values/thread; 1 row via smem for l/r) ----
        float a0, a1, ap;
        if (g == 0) {
            const float* pC = prevS + (t & 3) * BUF;
            const float* pP = prevS + ((t + 3) & 3) * BUF;
            a0 = pC[(kRows - 1) * kNX + c];   // h^t   row r0-1 (ghost center)
            a1 = pC[(kRows - 2) * kNX + c];   // h^t   row r0-2 (ghost's up)
            ap = pP[(kRows - 1) * kNX + c];   // h^t-1 row r0-1
            sm[SA + c] = a0;
        } else {
            const float* nC = nextS + (t & 3) * BUF;
            const float* nP = nextS + ((t + 3) & 3) * BUF;
            a0 = nC[c];                       // h^t   row r0+kRows
            a1 = nC[kNX + c];                 // h^t   row r0+kRows+1
            ap = nP[c];                       // h^t-1 row r0+kRows
            sm[SB + c] = a0;
        }

        const float inj1 = kDT2 * sm[WAV + t];
        const float inj2 = kDT2 * sm[WAV + t + 1];

        // ---- phase 1: h^{t+1} on my rows (reads cur + registers only) ----
        if (active) phase(cur, bufI, hE, hO, a0, a0, inj1);

        __syncthreads();  // merged barrier: SA/SB staged rows AND bufI visible

        // ---- ghost-row intermediate h^{t+1} (register-only, folded coeff) ----
        if (active) {
            const int stg = (g == 0) ? SA : SB;
            float adj  = (g == 0) ? hE[0] : hE[H - 1];   // adjacent own row of h^t
            float s0   = (a1 + adj) + (sm[stg + c - 1] + sm[stg + c + 1]);
            float lapU = fmaf(a0, -4.0f, s0);
            extI = fmaf(c2e, lapU, fmaf(2.0f, a0, -ap));
            if (srcExt) extI += inj1;
        }

        // receiver gather for step t (reads bufI, own CTA)
        if (tid < cnt)
            outB[t * kNREC + smi[RK + tid]] = bufI[smi[ROFF + tid]];

        // ---- phase 2: h^{t+2} on my rows (ghosts come from extI registers) ----
        if (active) phase(bufI, bufO, hO, hE, extI, extI, inj2);

        cluster.sync();   // publish bufI (h^{t+1}) + bufO (h^{t+2})

        // receiver gather for step t+1 (bufO not rewritten until superstep s+2,
        // which is ordered after sync(s+1) > this read)
        if (tid < cnt)
            outB[(t + 1) * kNREC + smi[RK + tid]] = bufO[smi[ROFF + tid]];
    }
}

extern "C" void kernel_launch(void* const* d_in, const int* in_sizes, int n_in,
                              void* d_out, int out_size)
{
    (void)in_sizes; (void)n_in; (void)out_size;
    const float* x   = (const float*)d_in[0];
    const float* vp  = (const float*)d_in[1];
    const int*   src = (const int*)d_in[2];
    const int*   rec = (const int*)d_in[3];
    float*       out = (float*)d_out;

    cudaFuncSetAttribute(wave_fd_kernel<16>,
                         cudaFuncAttributeMaxDynamicSharedMemorySize, smem_bytes(16));
    cudaFuncSetAttribute(wave_fd_kernel<16>,
                         cudaFuncAttributeNonPortableClusterSizeAllowed, 1);
    cudaFuncSetAttribute(wave_fd_kernel<8>,
                         cudaFuncAttributeMaxDynamicSharedMemorySize, smem_bytes(8));

    int maxCluster = 0;
    {
        cudaLaunchConfig_t probe = {};
        probe.gridDim          = dim3(kB * 16, 1, 1);
        probe.blockDim         = dim3(kThreads, 1, 1);
        probe.dynamicSmemBytes = smem_bytes(16);
        cudaOccupancyMaxPotentialClusterSize(&maxCluster, (const void*)wave_fd_kernel<16>, &probe);
    }

    cudaLaunchAttribute attr[1];
    attr[0].id = cudaLaunchAttributeClusterDimension;
    attr[0].val.clusterDim.y = 1;
    attr[0].val.clusterDim.z = 1;

    cudaLaunchConfig_t cfg = {};
    cfg.blockDim = dim3(kThreads, 1, 1);
    cfg.stream   = 0;
    cfg.attrs    = attr;
    cfg.numAttrs = 1;

    if (maxCluster >= 16) {
        cfg.gridDim              = dim3(kB * 16, 1, 1);
        cfg.dynamicSmemBytes     = smem_bytes(16);
        attr[0].val.clusterDim.x = 16;
        cudaLaunchKernelEx(&cfg, wave_fd_kernel<16>, x, vp, src, rec, out);
    } else {
        cfg.gridDim              = dim3(kB * 8, 1, 1);
        cfg.dynamicSmemBytes     = smem_bytes(8);
        attr[0].val.clusterDim.x = 8;
        cudaLaunchKernelEx(&cfg, wave_fd_kernel<8>, x, vp, src, rec, out);
    }
}